// round 1
// baseline (speedup 1.0000x reference)
#include <cuda_runtime.h>
#include <math.h>

// ---------------- problem constants ----------------
#define NB   4
#define TT   2048
#define CEMB 768
#define C3   (3 * CEMB)       // 2304
#define HID  (4 * CEMB)       // 3072
#define NH   12
#define HD   64
#define BT   (NB * TT)        // 8192
#define LNEPS 1e-5f

// ---------------- scratch (static device globals; no allocs allowed) ----------
__device__ float g_ln [BT * CEMB];   // layernorm output (reused for ln1 and ln2)
__device__ float g_qkv[BT * C3];     // qkv projection
__device__ float g_att[BT * CEMB];   // attention output (pre-W_o)
__device__ float g_x1 [BT * CEMB];   // x + attn
__device__ float g_h  [BT * HID];    // gelu(fc)

// ---------------- layernorm: one block per row ----------------
__global__ __launch_bounds__(256) void ln_kernel(
    const float* __restrict__ x, const float* __restrict__ g,
    const float* __restrict__ b, float* __restrict__ out)
{
    int row = blockIdx.x;
    int tid = threadIdx.x;
    const float* xr = x + (size_t)row * CEMB;

    float v[3];
#pragma unroll
    for (int i = 0; i < 3; i++) v[i] = xr[tid + i * 256];

    float s = v[0] + v[1] + v[2];
    float q = v[0] * v[0] + v[1] * v[1] + v[2] * v[2];

    __shared__ float ssum[8], ssq[8];
#pragma unroll
    for (int o = 16; o > 0; o >>= 1) {
        s += __shfl_xor_sync(0xffffffffu, s, o);
        q += __shfl_xor_sync(0xffffffffu, q, o);
    }
    if ((tid & 31) == 0) { ssum[tid >> 5] = s; ssq[tid >> 5] = q; }
    __syncthreads();
    if (tid < 32) {
        s = (tid < 8) ? ssum[tid] : 0.f;
        q = (tid < 8) ? ssq [tid] : 0.f;
#pragma unroll
        for (int o = 4; o > 0; o >>= 1) {
            s += __shfl_xor_sync(0xffffffffu, s, o);
            q += __shfl_xor_sync(0xffffffffu, q, o);
        }
        if (tid == 0) { ssum[0] = s; ssq[0] = q; }
    }
    __syncthreads();

    float mean = ssum[0] * (1.0f / CEMB);
    float var  = ssq[0]  * (1.0f / CEMB) - mean * mean;
    float rstd = rsqrtf(var + LNEPS);

    float* orow = out + (size_t)row * CEMB;
#pragma unroll
    for (int i = 0; i < 3; i++) {
        int c = tid + i * 256;
        orow[c] = (v[i] - mean) * rstd * g[c] + b[c];
    }
}

// ---------------- SGEMM: C = A[M,K] @ B[K,N] (+epilogue) ----------------
// 128x128 block tile, BK=16, 256 threads, 8x8 per thread.
// EPI: 0 = none, 1 = add residual R, 2 = exact gelu
template <int EPI>
__global__ __launch_bounds__(256) void sgemm_kernel(
    const float* __restrict__ A, const float* __restrict__ Bm,
    const float* __restrict__ R, float* __restrict__ Cm,
    int M, int N, int K)
{
    const int BK = 16;
    __shared__ float As[BK][128];
    __shared__ float Bs[BK][128];

    int tid = threadIdx.x;
    int m0 = blockIdx.y * 128;
    int n0 = blockIdx.x * 128;
    int tx = tid % 16;
    int ty = tid / 16;

    float acc[8][8];
#pragma unroll
    for (int i = 0; i < 8; i++)
#pragma unroll
        for (int j = 0; j < 8; j++) acc[i][j] = 0.f;

    for (int k0 = 0; k0 < K; k0 += BK) {
#pragma unroll
        for (int it = 0; it < 2; it++) {
            int ar = tid / 4 + it * 64;
            int ac = (tid % 4) * 4;
            float4 av = *(const float4*)&A[(size_t)(m0 + ar) * K + k0 + ac];
            As[ac + 0][ar] = av.x;
            As[ac + 1][ar] = av.y;
            As[ac + 2][ar] = av.z;
            As[ac + 3][ar] = av.w;

            int br = tid / 32 + it * 8;
            int bc = (tid % 32) * 4;
            *(float4*)&Bs[br][bc] =
                *(const float4*)&Bm[(size_t)(k0 + br) * N + n0 + bc];
        }
        __syncthreads();

#pragma unroll
        for (int kk = 0; kk < BK; kk++) {
            float a[8], b[8];
            *(float4*)&a[0] = *(const float4*)&As[kk][ty * 4];
            *(float4*)&a[4] = *(const float4*)&As[kk][64 + ty * 4];
            *(float4*)&b[0] = *(const float4*)&Bs[kk][tx * 4];
            *(float4*)&b[4] = *(const float4*)&Bs[kk][64 + tx * 4];
#pragma unroll
            for (int i = 0; i < 8; i++)
#pragma unroll
                for (int j = 0; j < 8; j++) acc[i][j] += a[i] * b[j];
        }
        __syncthreads();
    }

#pragma unroll
    for (int i = 0; i < 8; i++) {
        int row = m0 + ((i < 4) ? (ty * 4 + i) : (64 + ty * 4 + (i - 4)));
#pragma unroll
        for (int jb = 0; jb < 2; jb++) {
            int col = n0 + jb * 64 + tx * 4;
            float4 v;
            v.x = acc[i][jb * 4 + 0];
            v.y = acc[i][jb * 4 + 1];
            v.z = acc[i][jb * 4 + 2];
            v.w = acc[i][jb * 4 + 3];
            if (EPI == 1) {
                float4 r = *(const float4*)&R[(size_t)row * N + col];
                v.x += r.x; v.y += r.y; v.z += r.z; v.w += r.w;
            } else if (EPI == 2) {
                v.x = 0.5f * v.x * (1.0f + erff(v.x * 0.70710678118654752f));
                v.y = 0.5f * v.y * (1.0f + erff(v.y * 0.70710678118654752f));
                v.z = 0.5f * v.z * (1.0f + erff(v.z * 0.70710678118654752f));
                v.w = 0.5f * v.w * (1.0f + erff(v.w * 0.70710678118654752f));
            }
            *(float4*)&Cm[(size_t)row * N + col] = v;
        }
    }
}

// ---------------- flash attention (causal, fp32) ----------------
// grid: (T/128, NH, NB). 128 threads; thread t owns query q = qt*128 + t.
// Online softmax with per-32-key tile rescale. K/V tiles staged in SMEM.
__global__ __launch_bounds__(128) void attn_kernel(
    const float* __restrict__ qkv, float* __restrict__ y)
{
    const int BN = 32;
    const float scale = 0.125f;  // 1/sqrt(64)

    int qt  = blockIdx.x;
    int h   = blockIdx.y;
    int b   = blockIdx.z;
    int tid = threadIdx.x;
    int q_idx = qt * 128 + tid;

    const size_t base = (size_t)b * TT * C3;

    float qreg[HD];
    {
        const float* qp = qkv + base + (size_t)q_idx * C3 + h * HD;
#pragma unroll
        for (int d = 0; d < HD; d += 4) {
            float4 t4 = *(const float4*)&qp[d];
            qreg[d] = t4.x; qreg[d + 1] = t4.y; qreg[d + 2] = t4.z; qreg[d + 3] = t4.w;
        }
    }

    float o[HD];
#pragma unroll
    for (int d = 0; d < HD; d++) o[d] = 0.f;
    float m = -INFINITY, l = 0.f;

    __shared__ float Ks[BN][HD];
    __shared__ float Vs[BN][HD];
    __shared__ float Ssh[BN][128];

    int kend = qt * 128 + 128;  // block's max visible key (exclusive)

    for (int k0 = 0; k0 < kend; k0 += BN) {
        // stage K and V tiles: 32 rows x 64 floats each
#pragma unroll
        for (int it = 0; it < 4; it++) {
            int idx = tid + it * 128;       // float4 index, 0..511
            int r  = idx / 16;
            int c4 = (idx % 16) * 4;
            const float* kp = qkv + base + (size_t)(k0 + r) * C3 + CEMB + h * HD + c4;
            *(float4*)&Ks[r][c4] = *(const float4*)kp;
            const float* vp = qkv + base + (size_t)(k0 + r) * C3 + 2 * CEMB + h * HD + c4;
            *(float4*)&Vs[r][c4] = *(const float4*)vp;
        }
        __syncthreads();

        // scores
        float tmax = -INFINITY;
        for (int j = 0; j < BN; j++) {
            float s = 0.f;
#pragma unroll
            for (int d = 0; d < HD; d += 4) {
                float4 kv = *(const float4*)&Ks[j][d];
                s += qreg[d] * kv.x + qreg[d + 1] * kv.y
                   + qreg[d + 2] * kv.z + qreg[d + 3] * kv.w;
            }
            s *= scale;
            if (k0 + j > q_idx) s = -INFINITY;
            Ssh[j][tid] = s;
            tmax = fmaxf(tmax, s);
        }

        float mnew  = fmaxf(m, tmax);
        float alpha = __expf(m - mnew);
        l *= alpha;
#pragma unroll
        for (int d = 0; d < HD; d++) o[d] *= alpha;

        // accumulate P @ V
        for (int j = 0; j < BN; j++) {
            float p = __expf(Ssh[j][tid] - mnew);
            l += p;
#pragma unroll
            for (int d = 0; d < HD; d += 4) {
                float4 vv = *(const float4*)&Vs[j][d];
                o[d]     += p * vv.x;
                o[d + 1] += p * vv.y;
                o[d + 2] += p * vv.z;
                o[d + 3] += p * vv.w;
            }
        }
        m = mnew;
        __syncthreads();
    }

    float rl = 1.0f / l;
    float* yp = y + (size_t)(b * TT + q_idx) * CEMB + h * HD;
#pragma unroll
    for (int d = 0; d < HD; d += 4) {
        float4 t4;
        t4.x = o[d] * rl; t4.y = o[d + 1] * rl;
        t4.z = o[d + 2] * rl; t4.w = o[d + 3] * rl;
        *(float4*)&yp[d] = t4;
    }
}

// ---------------- launch ----------------
extern "C" void kernel_launch(void* const* d_in, const int* in_sizes, int n_in,
                              void* d_out, int out_size)
{
    (void)in_sizes; (void)n_in; (void)out_size;
    const float* x      = (const float*)d_in[0];
    const float* ln1_g  = (const float*)d_in[1];
    const float* ln1_b  = (const float*)d_in[2];
    const float* W_attn = (const float*)d_in[3];
    const float* W_o    = (const float*)d_in[4];
    const float* ln2_g  = (const float*)d_in[5];
    const float* ln2_b  = (const float*)d_in[6];
    const float* W_fc   = (const float*)d_in[7];
    const float* W_proj = (const float*)d_in[8];
    float* out = (float*)d_out;

    float *p_ln, *p_qkv, *p_att, *p_x1, *p_h;
    cudaGetSymbolAddress((void**)&p_ln,  g_ln);
    cudaGetSymbolAddress((void**)&p_qkv, g_qkv);
    cudaGetSymbolAddress((void**)&p_att, g_att);
    cudaGetSymbolAddress((void**)&p_x1,  g_x1);
    cudaGetSymbolAddress((void**)&p_h,   g_h);

    // 1. ln1
    ln_kernel<<<BT, 256>>>(x, ln1_g, ln1_b, p_ln);

    // 2. qkv = ln1 @ W_attn   [8192,768]x[768,2304]
    sgemm_kernel<0><<<dim3(C3 / 128, BT / 128), 256>>>(
        p_ln, W_attn, nullptr, p_qkv, BT, C3, CEMB);

    // 3. causal attention -> g_att [8192,768]
    attn_kernel<<<dim3(TT / 128, NH, NB), 128>>>(p_qkv, p_att);

    // 4. x1 = att @ W_o + x   [8192,768]x[768,768]
    sgemm_kernel<1><<<dim3(CEMB / 128, BT / 128), 256>>>(
        p_att, W_o, x, p_x1, BT, CEMB, CEMB);

    // 5. ln2
    ln_kernel<<<BT, 256>>>(p_x1, ln2_g, ln2_b, p_ln);

    // 6. h = gelu(ln2 @ W_fc)  [8192,768]x[768,3072]
    sgemm_kernel<2><<<dim3(HID / 128, BT / 128), 256>>>(
        p_ln, W_fc, nullptr, p_h, BT, HID, CEMB);

    // 7. out = h @ W_proj + x1 [8192,3072]x[3072,768]
    sgemm_kernel<1><<<dim3(CEMB / 128, BT / 128), 256>>>(
        p_h, W_proj, p_x1, out, BT, CEMB, HID);
}

// round 3
// speedup vs baseline: 1.8313x; 1.8313x over previous
#include <cuda_runtime.h>
#include <math.h>
#include <stdint.h>

// ---------------- problem constants ----------------
#define NB   4
#define TT   2048
#define CEMB 768
#define C3   (3 * CEMB)       // 2304
#define HID  (4 * CEMB)       // 3072
#define NH   12
#define HD   64
#define BT   (NB * TT)        // 8192
#define LNEPS 1e-5f

// GEMM tiling
#define BK     32
#define KPAD   36                      // 32 + 4 pad -> conflict-free frag loads
#define STG_FL (128 * KPAD)            // floats per operand per stage (4608)
#define STAGE_FL (2 * STG_FL)          // A + B per stage (9216 floats)
#define GEMM_SMEM (2 * STAGE_FL * 4)   // 2 stages, bytes (73728)

// ---------------- scratch ----------------
__device__ float g_ln [BT * CEMB];
__device__ float g_qkv[BT * C3];
__device__ float g_att[BT * CEMB];
__device__ float g_x1 [BT * CEMB];
__device__ float g_h  [BT * HID];
__device__ float g_wattT [C3 * CEMB];
__device__ float g_woT   [CEMB * CEMB];
__device__ float g_wfcT  [HID * CEMB];
__device__ float g_wprojT[CEMB * HID];

// ---------------- helpers ----------------
__device__ __forceinline__ uint32_t smem_u32(const void* p) {
    uint32_t a;
    asm("{ .reg .u64 t; cvta.to.shared.u64 t, %1; cvt.u32.u64 %0, t; }"
        : "=r"(a) : "l"(p));
    return a;
}

__device__ __forceinline__ float rtf32(float x) {
    uint32_t u;
    asm("cvt.rna.tf32.f32 %0, %1;" : "=r"(u) : "f"(x));
    return __uint_as_float(u);
}

__device__ __forceinline__ void cp16(uint32_t sa, const void* ga) {
    asm volatile("cp.async.cg.shared.global [%0], [%1], 16;"
                 :: "r"(sa), "l"(ga));
}

__device__ __forceinline__ void mma_tf32(float* d, const uint32_t* a,
                                         const uint32_t* b) {
    asm volatile(
        "mma.sync.aligned.m16n8k8.row.col.f32.tf32.tf32.f32 "
        "{%0,%1,%2,%3}, {%4,%5,%6,%7}, {%8,%9}, {%0,%1,%2,%3};"
        : "+f"(d[0]), "+f"(d[1]), "+f"(d[2]), "+f"(d[3])
        : "r"(a[0]), "r"(a[1]), "r"(a[2]), "r"(a[3]),
          "r"(b[0]), "r"(b[1]));
}

// ---------------- layernorm (output rounded to tf32) ----------------
__global__ __launch_bounds__(256) void ln_kernel(
    const float* __restrict__ x, const float* __restrict__ g,
    const float* __restrict__ b, float* __restrict__ out)
{
    int row = blockIdx.x;
    int tid = threadIdx.x;
    const float* xr = x + (size_t)row * CEMB;

    float v[3];
#pragma unroll
    for (int i = 0; i < 3; i++) v[i] = xr[tid + i * 256];

    float s = v[0] + v[1] + v[2];
    float q = v[0] * v[0] + v[1] * v[1] + v[2] * v[2];

    __shared__ float ssum[8], ssq[8];
#pragma unroll
    for (int o = 16; o > 0; o >>= 1) {
        s += __shfl_xor_sync(0xffffffffu, s, o);
        q += __shfl_xor_sync(0xffffffffu, q, o);
    }
    if ((tid & 31) == 0) { ssum[tid >> 5] = s; ssq[tid >> 5] = q; }
    __syncthreads();
    if (tid < 32) {
        s = (tid < 8) ? ssum[tid] : 0.f;
        q = (tid < 8) ? ssq [tid] : 0.f;
#pragma unroll
        for (int o = 4; o > 0; o >>= 1) {
            s += __shfl_xor_sync(0xffffffffu, s, o);
            q += __shfl_xor_sync(0xffffffffu, q, o);
        }
        if (tid == 0) { ssum[0] = s; ssq[0] = q; }
    }
    __syncthreads();

    float mean = ssum[0] * (1.0f / CEMB);
    float var  = ssq[0]  * (1.0f / CEMB) - mean * mean;
    float rstd = rsqrtf(var + LNEPS);

    float* orow = out + (size_t)row * CEMB;
#pragma unroll
    for (int i = 0; i < 3; i++) {
        int c = tid + i * 256;
        orow[c] = rtf32((v[i] - mean) * rstd * g[c] + b[c]);
    }
}

// ---------------- transpose + round: W[K,N] -> WT[N,K] ----------------
__global__ __launch_bounds__(256) void transpose_round(
    const float* __restrict__ W, float* __restrict__ WT, int K, int N)
{
    __shared__ float t[32][33];
    int bx = blockIdx.x * 32;   // N
    int by = blockIdx.y * 32;   // K
    int tx = threadIdx.x & 31, ty = threadIdx.x >> 5;
#pragma unroll
    for (int i = 0; i < 32; i += 8)
        t[ty + i][tx] = W[(size_t)(by + ty + i) * N + bx + tx];
    __syncthreads();
#pragma unroll
    for (int i = 0; i < 32; i += 8)
        WT[(size_t)(bx + ty + i) * K + by + tx] = rtf32(t[tx][ty + i]);
}

// ---------------- mma.sync tf32 GEMM: C = A[M,K] @ Bt[N,K]^T (+epi) ------
// 128x128 CTA tile, 8 warps (2x4), 64x32 warp tile, BK=32, 2-stage cp.async.
// EPI: 0 none, 1 +R, 2 gelu+round
template <int EPI>
__global__ __launch_bounds__(256) void mma_gemm(
    const float* __restrict__ A, const float* __restrict__ Bt,
    const float* __restrict__ R, float* __restrict__ C,
    int M, int N, int K)
{
    extern __shared__ float sm[];

    int tid  = threadIdx.x;
    int wid  = tid >> 5;
    int lane = tid & 31;
    int gid  = lane >> 2;     // group id (0..7)
    int tig  = lane & 3;      // thread in group (0..3)

    int m0 = blockIdx.y * 128, n0 = blockIdx.x * 128;
    int wm = (wid >> 2) * 64; // warp m offset within tile (0/64)
    int wn = (wid & 3) * 32;  // warp n offset within tile (0/32/64/96)

    uint32_t su = smem_u32(sm);

    float acc[4][4][4];
#pragma unroll
    for (int mi = 0; mi < 4; mi++)
#pragma unroll
        for (int ni = 0; ni < 4; ni++)
#pragma unroll
            for (int r = 0; r < 4; r++) acc[mi][ni][r] = 0.f;

    const int KS = K / BK;

    // per-thread load indices: 4 chunks for A, 4 for B per slab
    int lr[4], lc[4];
#pragma unroll
    for (int it = 0; it < 4; it++) {
        int idx = it * 256 + tid;
        lr[it] = idx >> 3;        // row 0..127
        lc[it] = idx & 7;         // float4 chunk 0..7
    }

#define LOAD_SLAB(k0, st) do {                                              \
    uint32_t base = su + (uint32_t)(st) * (STAGE_FL * 4);                   \
    _Pragma("unroll")                                                       \
    for (int it = 0; it < 4; it++) {                                        \
        uint32_t off = (uint32_t)lr[it] * (KPAD * 4) + (uint32_t)lc[it] * 16;\
        cp16(base + off,                                                    \
             A  + (size_t)(m0 + lr[it]) * K + (k0) + lc[it] * 4);           \
        cp16(base + (STG_FL * 4) + off,                                     \
             Bt + (size_t)(n0 + lr[it]) * K + (k0) + lc[it] * 4);           \
    }                                                                       \
    asm volatile("cp.async.commit_group;" ::: "memory");                    \
} while (0)

    LOAD_SLAB(0, 0);

    for (int i = 0; i < KS; i++) {
        int st = i & 1;
        if (i + 1 < KS) {
            LOAD_SLAB((i + 1) * BK, 1 - st);
            asm volatile("cp.async.wait_group 1;" ::: "memory");
        } else {
            asm volatile("cp.async.wait_group 0;" ::: "memory");
        }
        __syncthreads();

        const float* As = sm + st * STAGE_FL;
        const float* Bs = As + STG_FL;

#pragma unroll
        for (int kk = 0; kk < 4; kk++) {
            int kb = kk * 8;
            uint32_t a[4][4], b[4][2];
#pragma unroll
            for (int mi = 0; mi < 4; mi++) {
                int r0 = wm + mi * 16 + gid;
                a[mi][0] = __float_as_uint(As[(r0    ) * KPAD + kb + tig    ]);
                a[mi][1] = __float_as_uint(As[(r0 + 8) * KPAD + kb + tig    ]);
                a[mi][2] = __float_as_uint(As[(r0    ) * KPAD + kb + tig + 4]);
                a[mi][3] = __float_as_uint(As[(r0 + 8) * KPAD + kb + tig + 4]);
            }
#pragma unroll
            for (int ni = 0; ni < 4; ni++) {
                int c0 = wn + ni * 8 + gid;
                b[ni][0] = __float_as_uint(Bs[c0 * KPAD + kb + tig    ]);
                b[ni][1] = __float_as_uint(Bs[c0 * KPAD + kb + tig + 4]);
            }
#pragma unroll
            for (int mi = 0; mi < 4; mi++)
#pragma unroll
                for (int ni = 0; ni < 4; ni++)
                    mma_tf32(acc[mi][ni], a[mi], b[ni]);
        }
        __syncthreads();
    }

    // ---- epilogue ----
#pragma unroll
    for (int mi = 0; mi < 4; mi++) {
        int row0 = m0 + wm + mi * 16 + gid;
#pragma unroll
        for (int half = 0; half < 2; half++) {
            int row = row0 + half * 8;
#pragma unroll
            for (int ni = 0; ni < 4; ni++) {
                int col = n0 + wn + ni * 8 + tig * 2;
                float vx = acc[mi][ni][half * 2 + 0];
                float vy = acc[mi][ni][half * 2 + 1];
                if (EPI == 1) {
                    float2 rr = *(const float2*)&R[(size_t)row * N + col];
                    vx += rr.x; vy += rr.y;
                } else if (EPI == 2) {
                    vx = rtf32(0.5f * vx * (1.0f + erff(vx * 0.70710678118654752f)));
                    vy = rtf32(0.5f * vy * (1.0f + erff(vy * 0.70710678118654752f)));
                }
                float2 v; v.x = vx; v.y = vy;
                *(float2*)&C[(size_t)row * N + col] = v;
            }
        }
    }
#undef LOAD_SLAB
}

// ---------------- flash attention (causal, fp32) ----------------
__global__ __launch_bounds__(128) void attn_kernel(
    const float* __restrict__ qkv, float* __restrict__ y)
{
    const int BN = 32;
    const float scale = 0.125f;

    int qt  = blockIdx.x;
    int h   = blockIdx.y;
    int b   = blockIdx.z;
    int tid = threadIdx.x;
    int q_idx = qt * 128 + tid;

    const size_t base = (size_t)b * TT * C3;

    float qreg[HD];
    {
        const float* qp = qkv + base + (size_t)q_idx * C3 + h * HD;
#pragma unroll
        for (int d = 0; d < HD; d += 4) {
            float4 t4 = *(const float4*)&qp[d];
            qreg[d] = t4.x; qreg[d + 1] = t4.y; qreg[d + 2] = t4.z; qreg[d + 3] = t4.w;
        }
    }

    float o[HD];
#pragma unroll
    for (int d = 0; d < HD; d++) o[d] = 0.f;
    float m = -INFINITY, l = 0.f;

    __shared__ float Ks[BN][HD];
    __shared__ float Vs[BN][HD];
    __shared__ float Ssh[BN][128];

    int kend = qt * 128 + 128;

    for (int k0 = 0; k0 < kend; k0 += BN) {
#pragma unroll
        for (int it = 0; it < 4; it++) {
            int idx = tid + it * 128;
            int r  = idx / 16;
            int c4 = (idx % 16) * 4;
            const float* kp = qkv + base + (size_t)(k0 + r) * C3 + CEMB + h * HD + c4;
            *(float4*)&Ks[r][c4] = *(const float4*)kp;
            const float* vp = qkv + base + (size_t)(k0 + r) * C3 + 2 * CEMB + h * HD + c4;
            *(float4*)&Vs[r][c4] = *(const float4*)vp;
        }
        __syncthreads();

        float tmax = -INFINITY;
        for (int j = 0; j < BN; j++) {
            float s = 0.f;
#pragma unroll
            for (int d = 0; d < HD; d += 4) {
                float4 kv = *(const float4*)&Ks[j][d];
                s += qreg[d] * kv.x + qreg[d + 1] * kv.y
                   + qreg[d + 2] * kv.z + qreg[d + 3] * kv.w;
            }
            s *= scale;
            if (k0 + j > q_idx) s = -INFINITY;
            Ssh[j][tid] = s;
            tmax = fmaxf(tmax, s);
        }

        float mnew  = fmaxf(m, tmax);
        float alpha = __expf(m - mnew);
        l *= alpha;
#pragma unroll
        for (int d = 0; d < HD; d++) o[d] *= alpha;

        for (int j = 0; j < BN; j++) {
            float p = __expf(Ssh[j][tid] - mnew);
            l += p;
#pragma unroll
            for (int d = 0; d < HD; d += 4) {
                float4 vv = *(const float4*)&Vs[j][d];
                o[d]     += p * vv.x;
                o[d + 1] += p * vv.y;
                o[d + 2] += p * vv.z;
                o[d + 3] += p * vv.w;
            }
        }
        m = mnew;
        __syncthreads();
    }

    float rl = 1.0f / l;
    float* yp = y + (size_t)(b * TT + q_idx) * CEMB + h * HD;
#pragma unroll
    for (int d = 0; d < HD; d += 4) {
        float4 t4;
        t4.x = rtf32(o[d] * rl);     t4.y = rtf32(o[d + 1] * rl);
        t4.z = rtf32(o[d + 2] * rl); t4.w = rtf32(o[d + 3] * rl);
        *(float4*)&yp[d] = t4;
    }
}

// ---------------- launch ----------------
extern "C" void kernel_launch(void* const* d_in, const int* in_sizes, int n_in,
                              void* d_out, int out_size)
{
    (void)in_sizes; (void)n_in; (void)out_size;
    const float* x      = (const float*)d_in[0];
    const float* ln1_g  = (const float*)d_in[1];
    const float* ln1_b  = (const float*)d_in[2];
    const float* W_attn = (const float*)d_in[3];
    const float* W_o    = (const float*)d_in[4];
    const float* ln2_g  = (const float*)d_in[5];
    const float* ln2_b  = (const float*)d_in[6];
    const float* W_fc   = (const float*)d_in[7];
    const float* W_proj = (const float*)d_in[8];
    float* out = (float*)d_out;

    float *p_ln, *p_qkv, *p_att, *p_x1, *p_h;
    float *p_wattT, *p_woT, *p_wfcT, *p_wprojT;
    cudaGetSymbolAddress((void**)&p_ln,     g_ln);
    cudaGetSymbolAddress((void**)&p_qkv,    g_qkv);
    cudaGetSymbolAddress((void**)&p_att,    g_att);
    cudaGetSymbolAddress((void**)&p_x1,     g_x1);
    cudaGetSymbolAddress((void**)&p_h,      g_h);
    cudaGetSymbolAddress((void**)&p_wattT,  g_wattT);
    cudaGetSymbolAddress((void**)&p_woT,    g_woT);
    cudaGetSymbolAddress((void**)&p_wfcT,   g_wfcT);
    cudaGetSymbolAddress((void**)&p_wprojT, g_wprojT);

    cudaFuncSetAttribute(mma_gemm<0>, cudaFuncAttributeMaxDynamicSharedMemorySize, GEMM_SMEM);
    cudaFuncSetAttribute(mma_gemm<1>, cudaFuncAttributeMaxDynamicSharedMemorySize, GEMM_SMEM);
    cudaFuncSetAttribute(mma_gemm<2>, cudaFuncAttributeMaxDynamicSharedMemorySize, GEMM_SMEM);

    // weight transposes (+tf32 rounding)
    transpose_round<<<dim3(C3 / 32, CEMB / 32), 256>>>(W_attn, p_wattT, CEMB, C3);
    transpose_round<<<dim3(CEMB / 32, CEMB / 32), 256>>>(W_o, p_woT, CEMB, CEMB);
    transpose_round<<<dim3(HID / 32, CEMB / 32), 256>>>(W_fc, p_wfcT, CEMB, HID);
    transpose_round<<<dim3(CEMB / 32, HID / 32), 256>>>(W_proj, p_wprojT, HID, CEMB);

    // 1. ln1 (tf32-rounded output)
    ln_kernel<<<BT, 256>>>(x, ln1_g, ln1_b, p_ln);

    // 2. qkv = ln1 @ W_attn
    mma_gemm<0><<<dim3(C3 / 128, BT / 128), 256, GEMM_SMEM>>>(
        p_ln, p_wattT, nullptr, p_qkv, BT, C3, CEMB);

    // 3. attention (fp32; output tf32-rounded)
    attn_kernel<<<dim3(TT / 128, NH, NB), 128>>>(p_qkv, p_att);

    // 4. x1 = att @ W_o + x
    mma_gemm<1><<<dim3(CEMB / 128, BT / 128), 256, GEMM_SMEM>>>(
        p_att, p_woT, x, p_x1, BT, CEMB, CEMB);

    // 5. ln2
    ln_kernel<<<BT, 256>>>(p_x1, ln2_g, ln2_b, p_ln);

    // 6. h = gelu(ln2 @ W_fc)   (tf32-rounded output)
    mma_gemm<2><<<dim3(HID / 128, BT / 128), 256, GEMM_SMEM>>>(
        p_ln, p_wfcT, nullptr, p_h, BT, HID, CEMB);

    // 7. out = h @ W_proj + x1
    mma_gemm<1><<<dim3(CEMB / 128, BT / 128), 256, GEMM_SMEM>>>(
        p_h, p_wprojT, p_x1, out, BT, CEMB, HID);
}

// round 4
// speedup vs baseline: 3.2750x; 1.7883x over previous
#include <cuda_runtime.h>
#include <math.h>
#include <stdint.h>

// ---------------- problem constants ----------------
#define NB   4
#define TT   2048
#define CEMB 768
#define C3   (3 * CEMB)       // 2304
#define HID  (4 * CEMB)       // 3072
#define NH   12
#define HD   64
#define BT   (NB * TT)        // 8192
#define LNEPS 1e-5f
#define LOG2E 1.4426950408889634f

// GEMM tiling
#define BK     32
#define KPAD   36
#define STG_FL (128 * KPAD)
#define STAGE_FL (2 * STG_FL)
#define GEMM_SMEM (2 * STAGE_FL * 4)

// attention tiling
#define QT   128
#define KT   64
#define APAD 68
#define QS_FL (QT * APAD)            // 8704
#define KV_FL (KT * APAD)            // 4352
#define ASTG_FL (2 * KV_FL)          // 8704
#define ATT_SMEM ((QS_FL + 3 * ASTG_FL) * 4)  // 139264

// ---------------- scratch ----------------
__device__ float g_ln [BT * CEMB];
__device__ float g_qkv[BT * C3];
__device__ float g_vT [NB * NH * HD * TT];
__device__ float g_att[BT * CEMB];
__device__ float g_x1 [BT * CEMB];
__device__ float g_h  [BT * HID];
__device__ float g_wattT [C3 * CEMB];
__device__ float g_woT   [CEMB * CEMB];
__device__ float g_wfcT  [HID * CEMB];
__device__ float g_wprojT[CEMB * HID];

// ---------------- helpers ----------------
__device__ __forceinline__ uint32_t smem_u32(const void* p) {
    uint32_t a;
    asm("{ .reg .u64 t; cvta.to.shared.u64 t, %1; cvt.u32.u64 %0, t; }"
        : "=r"(a) : "l"(p));
    return a;
}

__device__ __forceinline__ float rtf32(float x) {
    uint32_t u;
    asm("cvt.rna.tf32.f32 %0, %1;" : "=r"(u) : "f"(x));
    return __uint_as_float(u);
}

__device__ __forceinline__ void cp16(uint32_t sa, const void* ga) {
    asm volatile("cp.async.cg.shared.global [%0], [%1], 16;"
                 :: "r"(sa), "l"(ga));
}

__device__ __forceinline__ void mma_tf32(float* d, const uint32_t* a,
                                         const uint32_t* b) {
    asm volatile(
        "mma.sync.aligned.m16n8k8.row.col.f32.tf32.tf32.f32 "
        "{%0,%1,%2,%3}, {%4,%5,%6,%7}, {%8,%9}, {%0,%1,%2,%3};"
        : "+f"(d[0]), "+f"(d[1]), "+f"(d[2]), "+f"(d[3])
        : "r"(a[0]), "r"(a[1]), "r"(a[2]), "r"(a[3]),
          "r"(b[0]), "r"(b[1]));
}

// ---------------- layernorm (output rounded to tf32) ----------------
__global__ __launch_bounds__(256) void ln_kernel(
    const float* __restrict__ x, const float* __restrict__ g,
    const float* __restrict__ b, float* __restrict__ out)
{
    int row = blockIdx.x;
    int tid = threadIdx.x;
    const float* xr = x + (size_t)row * CEMB;

    float v[3];
#pragma unroll
    for (int i = 0; i < 3; i++) v[i] = xr[tid + i * 256];

    float s = v[0] + v[1] + v[2];
    float q = v[0] * v[0] + v[1] * v[1] + v[2] * v[2];

    __shared__ float ssum[8], ssq[8];
#pragma unroll
    for (int o = 16; o > 0; o >>= 1) {
        s += __shfl_xor_sync(0xffffffffu, s, o);
        q += __shfl_xor_sync(0xffffffffu, q, o);
    }
    if ((tid & 31) == 0) { ssum[tid >> 5] = s; ssq[tid >> 5] = q; }
    __syncthreads();
    if (tid < 32) {
        s = (tid < 8) ? ssum[tid] : 0.f;
        q = (tid < 8) ? ssq [tid] : 0.f;
#pragma unroll
        for (int o = 4; o > 0; o >>= 1) {
            s += __shfl_xor_sync(0xffffffffu, s, o);
            q += __shfl_xor_sync(0xffffffffu, q, o);
        }
        if (tid == 0) { ssum[0] = s; ssq[0] = q; }
    }
    __syncthreads();

    float mean = ssum[0] * (1.0f / CEMB);
    float var  = ssq[0]  * (1.0f / CEMB) - mean * mean;
    float rstd = rsqrtf(var + LNEPS);

    float* orow = out + (size_t)row * CEMB;
#pragma unroll
    for (int i = 0; i < 3; i++) {
        int c = tid + i * 256;
        orow[c] = rtf32((v[i] - mean) * rstd * g[c] + b[c]);
    }
}

// ---------------- transpose + round: W[K,N] -> WT[N,K] ----------------
__global__ __launch_bounds__(256) void transpose_round(
    const float* __restrict__ W, float* __restrict__ WT, int K, int N)
{
    __shared__ float t[32][33];
    int bx = blockIdx.x * 32;
    int by = blockIdx.y * 32;
    int tx = threadIdx.x & 31, ty = threadIdx.x >> 5;
#pragma unroll
    for (int i = 0; i < 32; i += 8)
        t[ty + i][tx] = W[(size_t)(by + ty + i) * N + bx + tx];
    __syncthreads();
#pragma unroll
    for (int i = 0; i < 32; i += 8)
        WT[(size_t)(bx + ty + i) * K + by + tx] = rtf32(t[tx][ty + i]);
}

// ---------------- V transpose: qkv V-section -> g_vT[b,h][hd][key] -------
__global__ __launch_bounds__(256) void vtrans(
    const float* __restrict__ qkv, float* __restrict__ vT)
{
    __shared__ float t[32][33];
    int kb = blockIdx.x * 32;     // key
    int hb = blockIdx.y * 32;     // hd
    int bh = blockIdx.z;
    int b = bh / NH, h = bh % NH;
    int tx = threadIdx.x & 31, ty = threadIdx.x >> 5;
    const float* src = qkv + (size_t)b * TT * C3 + 2 * CEMB + h * HD;
#pragma unroll
    for (int i = 0; i < 32; i += 8)
        t[ty + i][tx] = src[(size_t)(kb + ty + i) * C3 + hb + tx];
    __syncthreads();
    float* dst = vT + (size_t)bh * HD * TT;
#pragma unroll
    for (int i = 0; i < 32; i += 8)
        dst[(size_t)(hb + ty + i) * TT + kb + tx] = t[tx][ty + i];
}

// ---------------- mma.sync tf32 GEMM: C = A[M,K] @ Bt[N,K]^T (+epi) ------
// EPI: 0 none, 1 +R, 2 gelu+round, 3 round
template <int EPI>
__global__ __launch_bounds__(256) void mma_gemm(
    const float* __restrict__ A, const float* __restrict__ Bt,
    const float* __restrict__ R, float* __restrict__ C,
    int M, int N, int K)
{
    extern __shared__ float sm[];

    int tid  = threadIdx.x;
    int wid  = tid >> 5;
    int lane = tid & 31;
    int gid  = lane >> 2;
    int tig  = lane & 3;

    int m0 = blockIdx.y * 128, n0 = blockIdx.x * 128;
    int wm = (wid >> 2) * 64;
    int wn = (wid & 3) * 32;

    uint32_t su = smem_u32(sm);

    float acc[4][4][4];
#pragma unroll
    for (int mi = 0; mi < 4; mi++)
#pragma unroll
        for (int ni = 0; ni < 4; ni++)
#pragma unroll
            for (int r = 0; r < 4; r++) acc[mi][ni][r] = 0.f;

    const int KS = K / BK;

    int lr[4], lc[4];
#pragma unroll
    for (int it = 0; it < 4; it++) {
        int idx = it * 256 + tid;
        lr[it] = idx >> 3;
        lc[it] = idx & 7;
    }

#define LOAD_SLAB(k0, st) do {                                              \
    uint32_t base = su + (uint32_t)(st) * (STAGE_FL * 4);                   \
    _Pragma("unroll")                                                       \
    for (int it = 0; it < 4; it++) {                                        \
        uint32_t off = (uint32_t)lr[it] * (KPAD * 4) + (uint32_t)lc[it] * 16;\
        cp16(base + off,                                                    \
             A  + (size_t)(m0 + lr[it]) * K + (k0) + lc[it] * 4);           \
        cp16(base + (STG_FL * 4) + off,                                     \
             Bt + (size_t)(n0 + lr[it]) * K + (k0) + lc[it] * 4);           \
    }                                                                       \
    asm volatile("cp.async.commit_group;" ::: "memory");                    \
} while (0)

    LOAD_SLAB(0, 0);

    for (int i = 0; i < KS; i++) {
        int st = i & 1;
        if (i + 1 < KS) {
            LOAD_SLAB((i + 1) * BK, 1 - st);
            asm volatile("cp.async.wait_group 1;" ::: "memory");
        } else {
            asm volatile("cp.async.wait_group 0;" ::: "memory");
        }
        __syncthreads();

        const float* As = sm + st * STAGE_FL;
        const float* Bs = As + STG_FL;

#pragma unroll
        for (int kk = 0; kk < 4; kk++) {
            int kb = kk * 8;
            uint32_t a[4][4], b[4][2];
#pragma unroll
            for (int mi = 0; mi < 4; mi++) {
                int r0 = wm + mi * 16 + gid;
                a[mi][0] = __float_as_uint(As[(r0    ) * KPAD + kb + tig    ]);
                a[mi][1] = __float_as_uint(As[(r0 + 8) * KPAD + kb + tig    ]);
                a[mi][2] = __float_as_uint(As[(r0    ) * KPAD + kb + tig + 4]);
                a[mi][3] = __float_as_uint(As[(r0 + 8) * KPAD + kb + tig + 4]);
            }
#pragma unroll
            for (int ni = 0; ni < 4; ni++) {
                int c0 = wn + ni * 8 + gid;
                b[ni][0] = __float_as_uint(Bs[c0 * KPAD + kb + tig    ]);
                b[ni][1] = __float_as_uint(Bs[c0 * KPAD + kb + tig + 4]);
            }
#pragma unroll
            for (int mi = 0; mi < 4; mi++)
#pragma unroll
                for (int ni = 0; ni < 4; ni++)
                    mma_tf32(acc[mi][ni], a[mi], b[ni]);
        }
        __syncthreads();
    }

#pragma unroll
    for (int mi = 0; mi < 4; mi++) {
        int row0 = m0 + wm + mi * 16 + gid;
#pragma unroll
        for (int half = 0; half < 2; half++) {
            int row = row0 + half * 8;
#pragma unroll
            for (int ni = 0; ni < 4; ni++) {
                int col = n0 + wn + ni * 8 + tig * 2;
                float vx = acc[mi][ni][half * 2 + 0];
                float vy = acc[mi][ni][half * 2 + 1];
                if (EPI == 1) {
                    float2 rr = *(const float2*)&R[(size_t)row * N + col];
                    vx += rr.x; vy += rr.y;
                } else if (EPI == 2) {
                    vx = rtf32(0.5f * vx * (1.0f + erff(vx * 0.70710678118654752f)));
                    vy = rtf32(0.5f * vy * (1.0f + erff(vy * 0.70710678118654752f)));
                } else if (EPI == 3) {
                    vx = rtf32(vx);
                    vy = rtf32(vy);
                }
                float2 v; v.x = vx; v.y = vy;
                *(float2*)&C[(size_t)row * N + col] = v;
            }
        }
    }
#undef LOAD_SLAB
}

// ---------------- MMA flash attention (causal, tf32) ----------------
// grid (TT/128, NH, NB), 256 threads = 8 warps; warp w owns q-rows 16w..16w+15.
// K-tiles of 64, 3-stage cp.async ring, S and PV via mma.sync tf32.
__global__ __launch_bounds__(256) void attn_mma(
    const float* __restrict__ qkv, const float* __restrict__ vT,
    float* __restrict__ y)
{
    extern __shared__ float sm[];
    int tid  = threadIdx.x;
    int wid  = tid >> 5;
    int lane = tid & 31;
    int gid  = lane >> 2;
    int tig  = lane & 3;

    int qt = blockIdx.x, h = blockIdx.y, b = blockIdx.z;
    int q0 = qt * QT;
    int ntiles = 2 * qt + 2;

    const float* qbase = qkv + (size_t)b * TT * C3 + h * HD;
    const float* kbase = qkv + (size_t)b * TT * C3 + CEMB + h * HD;
    const float* vbase = vT + (size_t)(b * NH + h) * HD * TT;

    uint32_t su = smem_u32(sm);

    // ---- load Q tile (group with tile 0) ----
#pragma unroll
    for (int it = 0; it < 8; it++) {
        int idx = it * 256 + tid;
        int r = idx >> 4, c = idx & 15;
        cp16(su + (uint32_t)(r * APAD + c * 4) * 4,
             qbase + (size_t)(q0 + r) * C3 + c * 4);
    }

#define LOAD_KV(k0, s) do {                                                  \
    uint32_t kdst = su + (uint32_t)(QS_FL + (s) * ASTG_FL) * 4;              \
    uint32_t vdst = kdst + KV_FL * 4;                                        \
    _Pragma("unroll")                                                        \
    for (int it = 0; it < 4; it++) {                                         \
        int idx = it * 256 + tid;                                            \
        int r = idx >> 4, c = idx & 15;                                      \
        uint32_t off = (uint32_t)(r * APAD + c * 4) * 4;                     \
        cp16(kdst + off, kbase + (size_t)((k0) + r) * C3 + c * 4);           \
        cp16(vdst + off, vbase + (size_t)r * TT + (k0) + c * 4);             \
    }                                                                        \
    asm volatile("cp.async.commit_group;" ::: "memory");                     \
} while (0)

    LOAD_KV(0, 0);          // group 1: Q + tile0
    LOAD_KV(KT, 1);         // group 2: tile1 (ntiles >= 2 always)

    uint32_t qf[8][4];
    float o[8][4];
#pragma unroll
    for (int ni = 0; ni < 8; ni++)
#pragma unroll
        for (int r = 0; r < 4; r++) o[ni][r] = 0.f;
    float m0v = -INFINITY, m1v = -INFINITY, l0 = 0.f, l1 = 0.f;

    int rw = wid * 16 + gid;          // local row (0..127), +8 second
    int quadbase = lane & 28;

    for (int i = 0; i < ntiles; i++) {
        if (i < ntiles - 1) {
            asm volatile("cp.async.wait_group 1;" ::: "memory");
        } else {
            asm volatile("cp.async.wait_group 0;" ::: "memory");
        }
        __syncthreads();

        if (i + 2 < ntiles) LOAD_KV((i + 2) * KT, (i + 2) % 3);

        if (i == 0) {
            // build Q fragments (scale folded; 0.125 is exact in tf32)
#pragma unroll
            for (int kk = 0; kk < 8; kk++) {
                qf[kk][0] = __float_as_uint(sm[(rw    ) * APAD + kk * 8 + tig    ] * 0.125f);
                qf[kk][1] = __float_as_uint(sm[(rw + 8) * APAD + kk * 8 + tig    ] * 0.125f);
                qf[kk][2] = __float_as_uint(sm[(rw    ) * APAD + kk * 8 + tig + 4] * 0.125f);
                qf[kk][3] = __float_as_uint(sm[(rw + 8) * APAD + kk * 8 + tig + 4] * 0.125f);
            }
        }

        int k0 = i * KT;
        bool active = (q0 + wid * 16 + 15) >= k0;
        if (active) {
            const float* Ks = sm + QS_FL + (i % 3) * ASTG_FL;
            const float* Vs = Ks + KV_FL;

            float sacc[8][4];
#pragma unroll
            for (int ni = 0; ni < 8; ni++)
#pragma unroll
                for (int r = 0; r < 4; r++) sacc[ni][r] = 0.f;

#pragma unroll
            for (int kk = 0; kk < 8; kk++) {
                int kb = kk * 8;
#pragma unroll
                for (int ni = 0; ni < 8; ni++) {
                    uint32_t bb[2];
                    bb[0] = __float_as_uint(Ks[(ni * 8 + gid) * APAD + kb + tig    ]);
                    bb[1] = __float_as_uint(Ks[(ni * 8 + gid) * APAD + kb + tig + 4]);
                    mma_tf32(sacc[ni], qf[kk], bb);
                }
            }

            // causal mask on the two diagonal tiles
            if (i >= ntiles - 2) {
                int row0 = q0 + rw;
#pragma unroll
                for (int ni = 0; ni < 8; ni++) {
#pragma unroll
                    for (int r = 0; r < 4; r++) {
                        int col = k0 + ni * 8 + 2 * tig + (r & 1);
                        int row = row0 + ((r >= 2) ? 8 : 0);
                        if (col > row) sacc[ni][r] = -INFINITY;
                    }
                }
            }

            // row max over this tile
            float t0 = -INFINITY, t1 = -INFINITY;
#pragma unroll
            for (int ni = 0; ni < 8; ni++) {
                t0 = fmaxf(t0, fmaxf(sacc[ni][0], sacc[ni][1]));
                t1 = fmaxf(t1, fmaxf(sacc[ni][2], sacc[ni][3]));
            }
            t0 = fmaxf(t0, __shfl_xor_sync(0xffffffffu, t0, 1));
            t0 = fmaxf(t0, __shfl_xor_sync(0xffffffffu, t0, 2));
            t1 = fmaxf(t1, __shfl_xor_sync(0xffffffffu, t1, 1));
            t1 = fmaxf(t1, __shfl_xor_sync(0xffffffffu, t1, 2));

            float mn0 = fmaxf(m0v, t0), mn1 = fmaxf(m1v, t1);
            float al0 = exp2f((m0v - mn0) * LOG2E);
            float al1 = exp2f((m1v - mn1) * LOG2E);
            m0v = mn0; m1v = mn1;
            l0 *= al0;  l1 *= al1;
#pragma unroll
            for (int ni = 0; ni < 8; ni++) {
                o[ni][0] *= al0; o[ni][1] *= al0;
                o[ni][2] *= al1; o[ni][3] *= al1;
            }

            // p = exp(s - m), rounded to tf32
#pragma unroll
            for (int ni = 0; ni < 8; ni++) {
                float p0 = exp2f((sacc[ni][0] - mn0) * LOG2E);
                float p1 = exp2f((sacc[ni][1] - mn0) * LOG2E);
                float p2 = exp2f((sacc[ni][2] - mn1) * LOG2E);
                float p3 = exp2f((sacc[ni][3] - mn1) * LOG2E);
                l0 += p0 + p1; l1 += p2 + p3;
                sacc[ni][0] = rtf32(p0); sacc[ni][1] = rtf32(p1);
                sacc[ni][2] = rtf32(p2); sacc[ni][3] = rtf32(p3);
            }

            // PV: a-frags via quad shuffles from sacc[kk]
#pragma unroll
            for (int kk = 0; kk < 8; kk++) {
                int s0 = quadbase | (tig >> 1);
                int s1 = quadbase | ((tig >> 1) + 2);
                float v00 = __shfl_sync(0xffffffffu, sacc[kk][0], s0);
                float v01 = __shfl_sync(0xffffffffu, sacc[kk][1], s0);
                float v10 = __shfl_sync(0xffffffffu, sacc[kk][2], s0);
                float v11 = __shfl_sync(0xffffffffu, sacc[kk][3], s0);
                float w00 = __shfl_sync(0xffffffffu, sacc[kk][0], s1);
                float w01 = __shfl_sync(0xffffffffu, sacc[kk][1], s1);
                float w10 = __shfl_sync(0xffffffffu, sacc[kk][2], s1);
                float w11 = __shfl_sync(0xffffffffu, sacc[kk][3], s1);
                uint32_t a[4];
                a[0] = __float_as_uint((tig & 1) ? v01 : v00);
                a[1] = __float_as_uint((tig & 1) ? v11 : v10);
                a[2] = __float_as_uint((tig & 1) ? w01 : w00);
                a[3] = __float_as_uint((tig & 1) ? w11 : w10);
                int kb = kk * 8;
#pragma unroll
                for (int ni = 0; ni < 8; ni++) {
                    uint32_t bb[2];
                    bb[0] = __float_as_uint(Vs[(ni * 8 + gid) * APAD + kb + tig    ]);
                    bb[1] = __float_as_uint(Vs[(ni * 8 + gid) * APAD + kb + tig + 4]);
                    mma_tf32(o[ni], a, bb);
                }
            }
        }
        __syncthreads();
    }

    // finalize: reduce l across quad, normalize, store
    l0 += __shfl_xor_sync(0xffffffffu, l0, 1);
    l0 += __shfl_xor_sync(0xffffffffu, l0, 2);
    l1 += __shfl_xor_sync(0xffffffffu, l1, 1);
    l1 += __shfl_xor_sync(0xffffffffu, l1, 2);
    float r0 = 1.0f / l0, r1 = 1.0f / l1;

    int grow0 = (b * TT + q0 + rw);
#pragma unroll
    for (int ni = 0; ni < 8; ni++) {
        int col = h * HD + ni * 8 + 2 * tig;
        float2 v0, v1;
        v0.x = rtf32(o[ni][0] * r0); v0.y = rtf32(o[ni][1] * r0);
        v1.x = rtf32(o[ni][2] * r1); v1.y = rtf32(o[ni][3] * r1);
        *(float2*)&y[(size_t)grow0 * CEMB + col] = v0;
        *(float2*)&y[(size_t)(grow0 + 8) * CEMB + col] = v1;
    }
#undef LOAD_KV
}

// ---------------- launch ----------------
extern "C" void kernel_launch(void* const* d_in, const int* in_sizes, int n_in,
                              void* d_out, int out_size)
{
    (void)in_sizes; (void)n_in; (void)out_size;
    const float* x      = (const float*)d_in[0];
    const float* ln1_g  = (const float*)d_in[1];
    const float* ln1_b  = (const float*)d_in[2];
    const float* W_attn = (const float*)d_in[3];
    const float* W_o    = (const float*)d_in[4];
    const float* ln2_g  = (const float*)d_in[5];
    const float* ln2_b  = (const float*)d_in[6];
    const float* W_fc   = (const float*)d_in[7];
    const float* W_proj = (const float*)d_in[8];
    float* out = (float*)d_out;

    float *p_ln, *p_qkv, *p_vT, *p_att, *p_x1, *p_h;
    float *p_wattT, *p_woT, *p_wfcT, *p_wprojT;
    cudaGetSymbolAddress((void**)&p_ln,     g_ln);
    cudaGetSymbolAddress((void**)&p_qkv,    g_qkv);
    cudaGetSymbolAddress((void**)&p_vT,     g_vT);
    cudaGetSymbolAddress((void**)&p_att,    g_att);
    cudaGetSymbolAddress((void**)&p_x1,     g_x1);
    cudaGetSymbolAddress((void**)&p_h,      g_h);
    cudaGetSymbolAddress((void**)&p_wattT,  g_wattT);
    cudaGetSymbolAddress((void**)&p_woT,    g_woT);
    cudaGetSymbolAddress((void**)&p_wfcT,   g_wfcT);
    cudaGetSymbolAddress((void**)&p_wprojT, g_wprojT);

    cudaFuncSetAttribute(mma_gemm<1>, cudaFuncAttributeMaxDynamicSharedMemorySize, GEMM_SMEM);
    cudaFuncSetAttribute(mma_gemm<2>, cudaFuncAttributeMaxDynamicSharedMemorySize, GEMM_SMEM);
    cudaFuncSetAttribute(mma_gemm<3>, cudaFuncAttributeMaxDynamicSharedMemorySize, GEMM_SMEM);
    cudaFuncSetAttribute(attn_mma, cudaFuncAttributeMaxDynamicSharedMemorySize, ATT_SMEM);

    // weight transposes (+tf32 rounding)
    transpose_round<<<dim3(C3 / 32, CEMB / 32), 256>>>(W_attn, p_wattT, CEMB, C3);
    transpose_round<<<dim3(CEMB / 32, CEMB / 32), 256>>>(W_o, p_woT, CEMB, CEMB);
    transpose_round<<<dim3(HID / 32, CEMB / 32), 256>>>(W_fc, p_wfcT, CEMB, HID);
    transpose_round<<<dim3(CEMB / 32, HID / 32), 256>>>(W_proj, p_wprojT, HID, CEMB);

    // 1. ln1 (tf32-rounded output)
    ln_kernel<<<BT, 256>>>(x, ln1_g, ln1_b, p_ln);

    // 2. qkv = ln1 @ W_attn (rounded output)
    mma_gemm<3><<<dim3(C3 / 128, BT / 128), 256, GEMM_SMEM>>>(
        p_ln, p_wattT, nullptr, p_qkv, BT, C3, CEMB);

    // 3a. transpose V per (b,h) -> [hd][key]
    vtrans<<<dim3(TT / 32, HD / 32, NB * NH), 256>>>(p_qkv, p_vT);

    // 3b. MMA flash attention
    attn_mma<<<dim3(TT / QT, NH, NB), 256, ATT_SMEM>>>(p_qkv, p_vT, p_att);

    // 4. x1 = att @ W_o + x
    mma_gemm<1><<<dim3(CEMB / 128, BT / 128), 256, GEMM_SMEM>>>(
        p_att, p_woT, x, p_x1, BT, CEMB, CEMB);

    // 5. ln2
    ln_kernel<<<BT, 256>>>(p_x1, ln2_g, ln2_b, p_ln);

    // 6. h = gelu(ln2 @ W_fc)
    mma_gemm<2><<<dim3(HID / 128, BT / 128), 256, GEMM_SMEM>>>(
        p_ln, p_wfcT, nullptr, p_h, BT, HID, CEMB);

    // 7. out = h @ W_proj + x1
    mma_gemm<1><<<dim3(CEMB / 128, BT / 128), 256, GEMM_SMEM>>>(
        p_h, p_wprojT, p_x1, out, BT, CEMB, HID);
}

// round 5
// speedup vs baseline: 5.7764x; 1.7638x over previous
#include <cuda_runtime.h>
#include <cuda_fp16.h>
#include <math.h>
#include <stdint.h>

// ---------------- problem constants ----------------
#define NB   4
#define TT   2048
#define CEMB 768
#define C3   (3 * CEMB)       // 2304
#define HID  (4 * CEMB)       // 3072
#define NH   12
#define HD   64
#define BT   (NB * TT)        // 8192
#define LNEPS 1e-5f
#define LOG2E 1.4426950408889634f

// GEMM tiling (halves)
#define BK      32                     // k-slab in halves
#define KPAD_H  40
#define STG_H   (128 * KPAD_H)         // halves per operand per stage (5120)
#define STAGE_H (2 * STG_H)            // A + B (10240 halves)
#define GEMM_SMEM (3 * STAGE_H * 2)    // 3 stages, bytes (61440)

// attention tiling (halves)
#define QT     128
#define KT     64
#define APAD_H 72
#define QS_H   (QT * APAD_H)           // 9216
#define KV_H   (KT * APAD_H)           // 4608
#define ASTG_H (2 * KV_H)              // 9216
#define ATT_SMEM ((QS_H + 3 * ASTG_H) * 2)   // 73728 bytes

// ---------------- scratch ----------------
__device__ __half g_ln [BT * CEMB];
__device__ __half g_qkv[BT * C3];
__device__ __half g_vT [NB * NH * HD * TT];
__device__ __half g_att[BT * CEMB];
__device__ float  g_x1 [BT * CEMB];
__device__ __half g_h  [BT * HID];
__device__ __half g_wattT [C3 * CEMB];
__device__ __half g_woT   [CEMB * CEMB];
__device__ __half g_wfcT  [HID * CEMB];
__device__ __half g_wprojT[CEMB * HID];

// ---------------- helpers ----------------
__device__ __forceinline__ uint32_t smem_u32(const void* p) {
    uint32_t a;
    asm("{ .reg .u64 t; cvta.to.shared.u64 t, %1; cvt.u32.u64 %0, t; }"
        : "=r"(a) : "l"(p));
    return a;
}

__device__ __forceinline__ void cp16(uint32_t sa, const void* ga) {
    asm volatile("cp.async.cg.shared.global [%0], [%1], 16;"
                 :: "r"(sa), "l"(ga));
}

__device__ __forceinline__ void mma_f16(float* d, const uint32_t* a,
                                        const uint32_t* b) {
    asm volatile(
        "mma.sync.aligned.m16n8k16.row.col.f32.f16.f16.f32 "
        "{%0,%1,%2,%3}, {%4,%5,%6,%7}, {%8,%9}, {%0,%1,%2,%3};"
        : "+f"(d[0]), "+f"(d[1]), "+f"(d[2]), "+f"(d[3])
        : "r"(a[0]), "r"(a[1]), "r"(a[2]), "r"(a[3]),
          "r"(b[0]), "r"(b[1]));
}

__device__ __forceinline__ uint32_t packh2(float x, float y) {
    __half2 h = __float22half2_rn(make_float2(x, y));
    return *(uint32_t*)&h;
}

// ---------------- layernorm (fp32 in, fp16 out) ----------------
__global__ __launch_bounds__(256) void ln_kernel(
    const float* __restrict__ x, const float* __restrict__ g,
    const float* __restrict__ b, __half* __restrict__ out)
{
    int row = blockIdx.x;
    int tid = threadIdx.x;
    const float* xr = x + (size_t)row * CEMB;

    float v[3];
#pragma unroll
    for (int i = 0; i < 3; i++) v[i] = xr[tid + i * 256];

    float s = v[0] + v[1] + v[2];
    float q = v[0] * v[0] + v[1] * v[1] + v[2] * v[2];

    __shared__ float ssum[8], ssq[8];
#pragma unroll
    for (int o = 16; o > 0; o >>= 1) {
        s += __shfl_xor_sync(0xffffffffu, s, o);
        q += __shfl_xor_sync(0xffffffffu, q, o);
    }
    if ((tid & 31) == 0) { ssum[tid >> 5] = s; ssq[tid >> 5] = q; }
    __syncthreads();
    if (tid < 32) {
        s = (tid < 8) ? ssum[tid] : 0.f;
        q = (tid < 8) ? ssq [tid] : 0.f;
#pragma unroll
        for (int o = 4; o > 0; o >>= 1) {
            s += __shfl_xor_sync(0xffffffffu, s, o);
            q += __shfl_xor_sync(0xffffffffu, q, o);
        }
        if (tid == 0) { ssum[0] = s; ssq[0] = q; }
    }
    __syncthreads();

    float mean = ssum[0] * (1.0f / CEMB);
    float var  = ssq[0]  * (1.0f / CEMB) - mean * mean;
    float rstd = rsqrtf(var + LNEPS);

    __half* orow = out + (size_t)row * CEMB;
#pragma unroll
    for (int i = 0; i < 3; i++) {
        int c = tid + i * 256;
        orow[c] = __float2half_rn((v[i] - mean) * rstd * g[c] + b[c]);
    }
}

// ---------------- transpose + to-half: W[K,N] -> WT[N,K] ----------------
__global__ __launch_bounds__(256) void transpose_half(
    const float* __restrict__ W, __half* __restrict__ WT, int K, int N)
{
    __shared__ float t[32][33];
    int bx = blockIdx.x * 32;
    int by = blockIdx.y * 32;
    int tx = threadIdx.x & 31, ty = threadIdx.x >> 5;
#pragma unroll
    for (int i = 0; i < 32; i += 8)
        t[ty + i][tx] = W[(size_t)(by + ty + i) * N + bx + tx];
    __syncthreads();
#pragma unroll
    for (int i = 0; i < 32; i += 8)
        WT[(size_t)(bx + ty + i) * K + by + tx] = __float2half_rn(t[tx][ty + i]);
}

// ---------------- V transpose: qkv V-section -> g_vT[b,h][hd][key] -------
__global__ __launch_bounds__(256) void vtrans(
    const __half* __restrict__ qkv, __half* __restrict__ vT)
{
    __shared__ float t[32][33];
    int kb = blockIdx.x * 32;     // key
    int hb = blockIdx.y * 32;     // hd
    int bh = blockIdx.z;
    int b = bh / NH, h = bh % NH;
    int tx = threadIdx.x & 31, ty = threadIdx.x >> 5;
    const __half* src = qkv + (size_t)b * TT * C3 + 2 * CEMB + h * HD;
#pragma unroll
    for (int i = 0; i < 32; i += 8)
        t[ty + i][tx] = __half2float(src[(size_t)(kb + ty + i) * C3 + hb + tx]);
    __syncthreads();
    __half* dst = vT + (size_t)bh * HD * TT;
#pragma unroll
    for (int i = 0; i < 32; i += 8)
        dst[(size_t)(hb + ty + i) * TT + kb + tx] = __float2half_rn(t[tx][ty + i]);
}

// ---------------- mma.sync fp16 GEMM: C = A[M,K] @ Bt[N,K]^T (+epi) ------
// 128x128 CTA tile, 8 warps (2x4), 64x32 warp tile, BK=32 halves, 3 stages.
// EPI: 0 -> half out, 1 -> float out + residual R, 2 -> gelu + half out
template <int EPI>
__global__ __launch_bounds__(256) void mma_gemm(
    const __half* __restrict__ A, const __half* __restrict__ Bt,
    const float* __restrict__ R, void* __restrict__ Cv,
    int M, int N, int K)
{
    extern __shared__ __half smh[];

    int tid  = threadIdx.x;
    int wid  = tid >> 5;
    int lane = tid & 31;
    int gid  = lane >> 2;
    int tig  = lane & 3;

    int m0 = blockIdx.y * 128, n0 = blockIdx.x * 128;
    int wm = (wid >> 2) * 64;
    int wn = (wid & 3) * 32;

    uint32_t su = smem_u32(smh);

    float acc[4][4][4];
#pragma unroll
    for (int mi = 0; mi < 4; mi++)
#pragma unroll
        for (int ni = 0; ni < 4; ni++)
#pragma unroll
            for (int r = 0; r < 4; r++) acc[mi][ni][r] = 0.f;

    const int KS = K / BK;

#define LOAD_SLAB(i) do {                                                   \
    int _k0 = (i) * BK;                                                     \
    uint32_t base = su + (uint32_t)((i) % 3) * (STAGE_H * 2);               \
    _Pragma("unroll")                                                       \
    for (int it = 0; it < 2; it++) {                                        \
        int idx = it * 256 + tid;                                           \
        int r = idx >> 2, c = idx & 3;                                      \
        uint32_t off = (uint32_t)r * (KPAD_H * 2) + (uint32_t)c * 16;       \
        cp16(base + off,                                                    \
             A  + (size_t)(m0 + r) * K + _k0 + c * 8);                      \
        cp16(base + (STG_H * 2) + off,                                      \
             Bt + (size_t)(n0 + r) * K + _k0 + c * 8);                      \
    }                                                                       \
    asm volatile("cp.async.commit_group;" ::: "memory");                    \
} while (0)

    LOAD_SLAB(0);
    LOAD_SLAB(1);

    for (int i = 0; i < KS; i++) {
        if (i + 2 < KS) {
            LOAD_SLAB(i + 2);
            asm volatile("cp.async.wait_group 2;" ::: "memory");
        } else if (i + 1 < KS) {
            asm volatile("cp.async.wait_group 1;" ::: "memory");
        } else {
            asm volatile("cp.async.wait_group 0;" ::: "memory");
        }
        __syncthreads();

        const __half* As = smh + (i % 3) * STAGE_H;
        const __half* Bs = As + STG_H;

#pragma unroll
        for (int kk = 0; kk < 2; kk++) {
            int kb = kk * 16;
            uint32_t a[4][4], b[4][2];
#pragma unroll
            for (int mi = 0; mi < 4; mi++) {
                int r0 = wm + mi * 16 + gid;
                a[mi][0] = *(const uint32_t*)&As[(r0    ) * KPAD_H + kb + 2 * tig    ];
                a[mi][1] = *(const uint32_t*)&As[(r0 + 8) * KPAD_H + kb + 2 * tig    ];
                a[mi][2] = *(const uint32_t*)&As[(r0    ) * KPAD_H + kb + 2 * tig + 8];
                a[mi][3] = *(const uint32_t*)&As[(r0 + 8) * KPAD_H + kb + 2 * tig + 8];
            }
#pragma unroll
            for (int ni = 0; ni < 4; ni++) {
                int c0 = wn + ni * 8 + gid;
                b[ni][0] = *(const uint32_t*)&Bs[c0 * KPAD_H + kb + 2 * tig    ];
                b[ni][1] = *(const uint32_t*)&Bs[c0 * KPAD_H + kb + 2 * tig + 8];
            }
#pragma unroll
            for (int mi = 0; mi < 4; mi++)
#pragma unroll
                for (int ni = 0; ni < 4; ni++)
                    mma_f16(acc[mi][ni], a[mi], b[ni]);
        }
        __syncthreads();
    }

    // ---- epilogue ----
#pragma unroll
    for (int mi = 0; mi < 4; mi++) {
        int row0 = m0 + wm + mi * 16 + gid;
#pragma unroll
        for (int half_ = 0; half_ < 2; half_++) {
            int row = row0 + half_ * 8;
#pragma unroll
            for (int ni = 0; ni < 4; ni++) {
                int col = n0 + wn + ni * 8 + tig * 2;
                float vx = acc[mi][ni][half_ * 2 + 0];
                float vy = acc[mi][ni][half_ * 2 + 1];
                if (EPI == 1) {
                    float* C = (float*)Cv;
                    float2 rr = *(const float2*)&R[(size_t)row * N + col];
                    float2 v; v.x = vx + rr.x; v.y = vy + rr.y;
                    *(float2*)&C[(size_t)row * N + col] = v;
                } else {
                    if (EPI == 2) {
                        vx = 0.5f * vx * (1.0f + erff(vx * 0.70710678118654752f));
                        vy = 0.5f * vy * (1.0f + erff(vy * 0.70710678118654752f));
                    }
                    __half* C = (__half*)Cv;
                    *(uint32_t*)&C[(size_t)row * N + col] = packh2(vx, vy);
                }
            }
        }
    }
#undef LOAD_SLAB
}

// ---------------- MMA flash attention (causal, fp16) ----------------
// grid (TT/128, NH, NB), 256 threads = 8 warps; warp w owns q-rows 16w..16w+15.
// K-tiles of 64, 3-stage cp.async ring, S and PV via mma.sync m16n8k16 fp16.
__global__ __launch_bounds__(256) void attn_mma(
    const __half* __restrict__ qkv, const __half* __restrict__ vT,
    __half* __restrict__ y)
{
    extern __shared__ __half smh[];
    int tid  = threadIdx.x;
    int wid  = tid >> 5;
    int lane = tid & 31;
    int gid  = lane >> 2;
    int tig  = lane & 3;

    int qt = blockIdx.x, h = blockIdx.y, b = blockIdx.z;
    int q0 = qt * QT;
    int ntiles = 2 * qt + 2;

    const __half* qbase = qkv + (size_t)b * TT * C3 + h * HD;
    const __half* kbase = qkv + (size_t)b * TT * C3 + CEMB + h * HD;
    const __half* vbase = vT + (size_t)(b * NH + h) * HD * TT;

    uint32_t su = smem_u32(smh);

    // ---- load Q tile (grouped with tile 0) ----
#pragma unroll
    for (int it = 0; it < 4; it++) {
        int idx = it * 256 + tid;
        int r = idx >> 3, c = idx & 7;
        cp16(su + (uint32_t)(r * APAD_H + c * 8) * 2,
             qbase + (size_t)(q0 + r) * C3 + c * 8);
    }

#define LOAD_KV(k0, s) do {                                                  \
    uint32_t kdst = su + (uint32_t)(QS_H + (s) * ASTG_H) * 2;                \
    uint32_t vdst = kdst + KV_H * 2;                                         \
    _Pragma("unroll")                                                        \
    for (int it = 0; it < 2; it++) {                                         \
        int idx = it * 256 + tid;                                            \
        int r = idx >> 3, c = idx & 7;                                       \
        uint32_t off = (uint32_t)(r * APAD_H + c * 8) * 2;                   \
        cp16(kdst + off, kbase + (size_t)((k0) + r) * C3 + c * 8);           \
        cp16(vdst + off, vbase + (size_t)r * TT + (k0) + c * 8);             \
    }                                                                        \
    asm volatile("cp.async.commit_group;" ::: "memory");                     \
} while (0)

    LOAD_KV(0, 0);          // group 1: Q + tile0
    LOAD_KV(KT, 1);         // group 2: tile1

    uint32_t qf[4][4];
    float o[8][4];
#pragma unroll
    for (int ni = 0; ni < 8; ni++)
#pragma unroll
        for (int r = 0; r < 4; r++) o[ni][r] = 0.f;
    float m0v = -INFINITY, m1v = -INFINITY, l0 = 0.f, l1 = 0.f;

    int rw = wid * 16 + gid;
    const __half2 hscale = __float2half2_rn(0.125f);

    for (int i = 0; i < ntiles; i++) {
        if (i < ntiles - 1) {
            asm volatile("cp.async.wait_group 1;" ::: "memory");
        } else {
            asm volatile("cp.async.wait_group 0;" ::: "memory");
        }
        __syncthreads();

        if (i + 2 < ntiles) LOAD_KV((i + 2) * KT, (i + 2) % 3);

        if (i == 0) {
            // Q fragments, scale folded (0.125 exact in fp16)
#pragma unroll
            for (int kk = 0; kk < 4; kk++) {
                int kb = kk * 16;
                __half2 h0 = __hmul2(*(const __half2*)&smh[(rw    ) * APAD_H + kb + 2 * tig    ], hscale);
                __half2 h1 = __hmul2(*(const __half2*)&smh[(rw + 8) * APAD_H + kb + 2 * tig    ], hscale);
                __half2 h2 = __hmul2(*(const __half2*)&smh[(rw    ) * APAD_H + kb + 2 * tig + 8], hscale);
                __half2 h3 = __hmul2(*(const __half2*)&smh[(rw + 8) * APAD_H + kb + 2 * tig + 8], hscale);
                qf[kk][0] = *(uint32_t*)&h0; qf[kk][1] = *(uint32_t*)&h1;
                qf[kk][2] = *(uint32_t*)&h2; qf[kk][3] = *(uint32_t*)&h3;
            }
        }

        int k0 = i * KT;
        bool active = (q0 + wid * 16 + 15) >= k0;
        if (active) {
            const __half* Ks = smh + QS_H + (i % 3) * ASTG_H;
            const __half* Vs = Ks + KV_H;

            float sacc[8][4];
#pragma unroll
            for (int ni = 0; ni < 8; ni++)
#pragma unroll
                for (int r = 0; r < 4; r++) sacc[ni][r] = 0.f;

#pragma unroll
            for (int kk = 0; kk < 4; kk++) {
                int kb = kk * 16;
#pragma unroll
                for (int ni = 0; ni < 8; ni++) {
                    uint32_t bb[2];
                    bb[0] = *(const uint32_t*)&Ks[(ni * 8 + gid) * APAD_H + kb + 2 * tig    ];
                    bb[1] = *(const uint32_t*)&Ks[(ni * 8 + gid) * APAD_H + kb + 2 * tig + 8];
                    mma_f16(sacc[ni], qf[kk], bb);
                }
            }

            // causal mask on the two diagonal tiles
            if (i >= ntiles - 2) {
                int row0 = q0 + rw;
#pragma unroll
                for (int ni = 0; ni < 8; ni++) {
#pragma unroll
                    for (int r = 0; r < 4; r++) {
                        int col = k0 + ni * 8 + 2 * tig + (r & 1);
                        int row = row0 + ((r >= 2) ? 8 : 0);
                        if (col > row) sacc[ni][r] = -INFINITY;
                    }
                }
            }

            // row max over this tile
            float t0 = -INFINITY, t1 = -INFINITY;
#pragma unroll
            for (int ni = 0; ni < 8; ni++) {
                t0 = fmaxf(t0, fmaxf(sacc[ni][0], sacc[ni][1]));
                t1 = fmaxf(t1, fmaxf(sacc[ni][2], sacc[ni][3]));
            }
            t0 = fmaxf(t0, __shfl_xor_sync(0xffffffffu, t0, 1));
            t0 = fmaxf(t0, __shfl_xor_sync(0xffffffffu, t0, 2));
            t1 = fmaxf(t1, __shfl_xor_sync(0xffffffffu, t1, 1));
            t1 = fmaxf(t1, __shfl_xor_sync(0xffffffffu, t1, 2));

            float mn0 = fmaxf(m0v, t0), mn1 = fmaxf(m1v, t1);
            float al0 = exp2f((m0v - mn0) * LOG2E);
            float al1 = exp2f((m1v - mn1) * LOG2E);
            m0v = mn0; m1v = mn1;
            l0 *= al0;  l1 *= al1;
#pragma unroll
            for (int ni = 0; ni < 8; ni++) {
                o[ni][0] *= al0; o[ni][1] *= al0;
                o[ni][2] *= al1; o[ni][3] *= al1;
            }

            // p = exp(s - m); pack P fragments directly (C-layout == A-layout)
            uint32_t pf[4][4];
#pragma unroll
            for (int kk = 0; kk < 4; kk++) {
                float p00 = exp2f((sacc[2 * kk    ][0] - mn0) * LOG2E);
                float p01 = exp2f((sacc[2 * kk    ][1] - mn0) * LOG2E);
                float p02 = exp2f((sacc[2 * kk    ][2] - mn1) * LOG2E);
                float p03 = exp2f((sacc[2 * kk    ][3] - mn1) * LOG2E);
                float p10 = exp2f((sacc[2 * kk + 1][0] - mn0) * LOG2E);
                float p11 = exp2f((sacc[2 * kk + 1][1] - mn0) * LOG2E);
                float p12 = exp2f((sacc[2 * kk + 1][2] - mn1) * LOG2E);
                float p13 = exp2f((sacc[2 * kk + 1][3] - mn1) * LOG2E);
                l0 += p00 + p01 + p10 + p11;
                l1 += p02 + p03 + p12 + p13;
                pf[kk][0] = packh2(p00, p01);
                pf[kk][1] = packh2(p02, p03);
                pf[kk][2] = packh2(p10, p11);
                pf[kk][3] = packh2(p12, p13);
            }

            // PV
#pragma unroll
            for (int kk = 0; kk < 4; kk++) {
                int kb = kk * 16;
#pragma unroll
                for (int ni = 0; ni < 8; ni++) {
                    uint32_t bb[2];
                    bb[0] = *(const uint32_t*)&Vs[(ni * 8 + gid) * APAD_H + kb + 2 * tig    ];
                    bb[1] = *(const uint32_t*)&Vs[(ni * 8 + gid) * APAD_H + kb + 2 * tig + 8];
                    mma_f16(o[ni], pf[kk], bb);
                }
            }
        }
        __syncthreads();
    }

    // finalize
    l0 += __shfl_xor_sync(0xffffffffu, l0, 1);
    l0 += __shfl_xor_sync(0xffffffffu, l0, 2);
    l1 += __shfl_xor_sync(0xffffffffu, l1, 1);
    l1 += __shfl_xor_sync(0xffffffffu, l1, 2);
    float r0 = 1.0f / l0, r1 = 1.0f / l1;

    int grow0 = (b * TT + q0 + rw);
#pragma unroll
    for (int ni = 0; ni < 8; ni++) {
        int col = h * HD + ni * 8 + 2 * tig;
        *(uint32_t*)&y[(size_t)grow0 * CEMB + col]       = packh2(o[ni][0] * r0, o[ni][1] * r0);
        *(uint32_t*)&y[(size_t)(grow0 + 8) * CEMB + col] = packh2(o[ni][2] * r1, o[ni][3] * r1);
    }
#undef LOAD_KV
}

// ---------------- launch ----------------
extern "C" void kernel_launch(void* const* d_in, const int* in_sizes, int n_in,
                              void* d_out, int out_size)
{
    (void)in_sizes; (void)n_in; (void)out_size;
    const float* x      = (const float*)d_in[0];
    const float* ln1_g  = (const float*)d_in[1];
    const float* ln1_b  = (const float*)d_in[2];
    const float* W_attn = (const float*)d_in[3];
    const float* W_o    = (const float*)d_in[4];
    const float* ln2_g  = (const float*)d_in[5];
    const float* ln2_b  = (const float*)d_in[6];
    const float* W_fc   = (const float*)d_in[7];
    const float* W_proj = (const float*)d_in[8];
    float* out = (float*)d_out;

    __half *p_ln, *p_qkv, *p_vT, *p_att, *p_h;
    __half *p_wattT, *p_woT, *p_wfcT, *p_wprojT;
    float *p_x1;
    cudaGetSymbolAddress((void**)&p_ln,     g_ln);
    cudaGetSymbolAddress((void**)&p_qkv,    g_qkv);
    cudaGetSymbolAddress((void**)&p_vT,     g_vT);
    cudaGetSymbolAddress((void**)&p_att,    g_att);
    cudaGetSymbolAddress((void**)&p_x1,     g_x1);
    cudaGetSymbolAddress((void**)&p_h,      g_h);
    cudaGetSymbolAddress((void**)&p_wattT,  g_wattT);
    cudaGetSymbolAddress((void**)&p_woT,    g_woT);
    cudaGetSymbolAddress((void**)&p_wfcT,   g_wfcT);
    cudaGetSymbolAddress((void**)&p_wprojT, g_wprojT);

    cudaFuncSetAttribute(mma_gemm<0>, cudaFuncAttributeMaxDynamicSharedMemorySize, GEMM_SMEM);
    cudaFuncSetAttribute(mma_gemm<1>, cudaFuncAttributeMaxDynamicSharedMemorySize, GEMM_SMEM);
    cudaFuncSetAttribute(mma_gemm<2>, cudaFuncAttributeMaxDynamicSharedMemorySize, GEMM_SMEM);
    cudaFuncSetAttribute(attn_mma, cudaFuncAttributeMaxDynamicSharedMemorySize, ATT_SMEM);

    // weight transposes (fp32 -> fp16)
    transpose_half<<<dim3(C3 / 32, CEMB / 32), 256>>>(W_attn, p_wattT, CEMB, C3);
    transpose_half<<<dim3(CEMB / 32, CEMB / 32), 256>>>(W_o, p_woT, CEMB, CEMB);
    transpose_half<<<dim3(HID / 32, CEMB / 32), 256>>>(W_fc, p_wfcT, CEMB, HID);
    transpose_half<<<dim3(CEMB / 32, HID / 32), 256>>>(W_proj, p_wprojT, HID, CEMB);

    // 1. ln1
    ln_kernel<<<BT, 256>>>(x, ln1_g, ln1_b, p_ln);

    // 2. qkv = ln1 @ W_attn (half out)
    mma_gemm<0><<<dim3(C3 / 128, BT / 128), 256, GEMM_SMEM>>>(
        p_ln, p_wattT, nullptr, p_qkv, BT, C3, CEMB);

    // 3a. transpose V per (b,h) -> [hd][key]
    vtrans<<<dim3(TT / 32, HD / 32, NB * NH), 256>>>(p_qkv, p_vT);

    // 3b. MMA flash attention (half out)
    attn_mma<<<dim3(TT / QT, NH, NB), 256, ATT_SMEM>>>(p_qkv, p_vT, p_att);

    // 4. x1 = att @ W_o + x (float out)
    mma_gemm<1><<<dim3(CEMB / 128, BT / 128), 256, GEMM_SMEM>>>(
        p_att, p_woT, x, p_x1, BT, CEMB, CEMB);

    // 5. ln2
    ln_kernel<<<BT, 256>>>(p_x1, ln2_g, ln2_b, p_ln);

    // 6. h = gelu(ln2 @ W_fc) (half out)
    mma_gemm<2><<<dim3(HID / 128, BT / 128), 256, GEMM_SMEM>>>(
        p_ln, p_wfcT, nullptr, p_h, BT, HID, CEMB);

    // 7. out = h @ W_proj + x1 (float out)
    mma_gemm<1><<<dim3(CEMB / 128, BT / 128), 256, GEMM_SMEM>>>(
        p_h, p_wprojT, p_x1, out, BT, CEMB, HID);
}